// round 16
// baseline (speedup 1.0000x reference)
#include <cuda_runtime.h>
#include <cuda_fp16.h>
#include <cstdint>

#define BATCH 4096
#define NF    8192
#define DIM   256
#define HEADS 4
#define CELLS 32
#define SK2   4            // gemm2 split-K

// ---------------- scratch (device globals; no allocs allowed) ----------------
__device__ __align__(16) __half g_xh[(size_t)BATCH * NF];   // x fp16 (67 MB)
__device__ float g_reps[NF * DIM];
__device__ __align__(16) __half g_bh16[NF * DIM];           // reps   [NF][DIM] fp16
__device__ __align__(16) __half g_bth[DIM * NF];            // reps^T [DIM][NF] fp16
__device__ __align__(16) __half g_part16[SK2][(size_t)BATCH * DIM];  // fp16 partials (8 MB)
__device__ __align__(16) __half g_ah[BATCH * DIM];          // hidden fp16

// ---------------- PTX helpers (base ISA only) ----------------
__device__ __forceinline__ uint32_t smem_u32(const void* p) {
    uint32_t a;
    asm("{ .reg .u64 t; cvta.to.shared.u64 t, %1; cvt.u32.u64 %0, t; }" : "=r"(a) : "l"(p));
    return a;
}
__device__ __forceinline__ void cp16(uint32_t d, const void* s) {
    asm volatile("cp.async.cg.shared.global [%0], [%1], 16;" :: "r"(d), "l"(s));
}
__device__ __forceinline__ void cp_commit() {
    asm volatile("cp.async.commit_group;" ::: "memory");
}
__device__ __forceinline__ void cp_wait0() {
    asm volatile("cp.async.wait_group 0;" ::: "memory");
}
__device__ __forceinline__ void cp_wait1() {
    asm volatile("cp.async.wait_group 1;" ::: "memory");
}
__device__ __forceinline__ void ldsm4(uint32_t& r0, uint32_t& r1, uint32_t& r2,
                                      uint32_t& r3, uint32_t a) {
    asm("ldmatrix.sync.aligned.m8n8.x4.shared.b16 {%0,%1,%2,%3}, [%4];"
        : "=r"(r0), "=r"(r1), "=r"(r2), "=r"(r3) : "r"(a));
}
__device__ __forceinline__ void mma16816(float* d, const uint32_t* a,
                                         uint32_t b0, uint32_t b1) {
    asm("mma.sync.aligned.m16n8k16.row.col.f32.f16.f16.f32 "
        "{%0,%1,%2,%3}, {%4,%5,%6,%7}, {%8,%9}, {%0,%1,%2,%3};"
        : "+f"(d[0]), "+f"(d[1]), "+f"(d[2]), "+f"(d[3])
        : "r"(a[0]), "r"(a[1]), "r"(a[2]), "r"(a[3]), "r"(b0), "r"(b1));
}

// smem tile: 128 rows x 64 fp16 = 128 B/row (8 16B chunks), swizzle c^(r&7)
#define OFF_A  0
#define OFF_B  16384
#define BUF_STRIDE 32768
#define N_STAGES 3
#define GEMM_SMEM (N_STAGES * BUF_STRIDE)    // 96 KB

__device__ __forceinline__ uint32_t tswz(int r, int c) {
    return (uint32_t)(r * 128 + ((c ^ (r & 7)) << 4));
}

// =====================================================================
// Kernel 1: reps — 2 rows per pass, smem partial-max reduction,
// fused straight fp16 output.
// =====================================================================
__global__ void reps_kernel(const float* __restrict__ proj,
                            const float* __restrict__ rw,
                            const float* __restrict__ rb,
                            const float* __restrict__ cb) {
    extern __shared__ float Wsh[];              // HEADS*CELLS*DIM floats (128KB)
    __shared__ float lat[2][DIM];
    __shared__ float part[2][HEADS * CELLS][33];
    __shared__ float sc[2][HEADS * CELLS];
    __shared__ float g_sh[2][HEADS];
    __shared__ int   w_sh[2][HEADS];
    __shared__ int   r_sh[2][HEADS];

    const int tid  = threadIdx.x;
    const int lane = tid & 31;
    const int warp = tid >> 5;

    for (int i = tid; i < HEADS * CELLS * DIM; i += 256)
        Wsh[i] = rw[i];
    __syncthreads();

    for (int row = blockIdx.x * 2; row < NF; row += gridDim.x * 2) {
        lat[0][tid] = proj[row * DIM + tid];
        lat[1][tid] = proj[(row + 1) * DIM + tid];
        __syncthreads();

        float la0[8], la1[8];
        #pragma unroll
        for (int i = 0; i < 8; ++i) {
            la0[i] = lat[0][lane + 32 * i];
            la1[i] = lat[1][lane + 32 * i];
        }

        #pragma unroll 1
        for (int pi = 0; pi < 16; ++pi) {
            const int p = warp * 16 + pi;
            const float* wrow = &Wsh[p * DIM];
            float m0 = -3.4e38f, m1 = -3.4e38f;
            #pragma unroll
            for (int i = 0; i < 8; ++i) {
                const float w = wrow[lane + 32 * i];
                m0 = fmaxf(m0, la0[i] + w);
                m1 = fmaxf(m1, la1[i] + w);
            }
            part[0][p][lane] = m0;
            part[1][p][lane] = m1;
        }
        __syncthreads();

        {
            const int rsel = tid >> 7;          // 0 or 1
            const int p = tid & 127;
            float m = -3.4e38f;
            #pragma unroll
            for (int i = 0; i < 32; ++i) m = fmaxf(m, part[rsel][p][i]);
            sc[rsel][p] = m + rb[p];
        }
        __syncthreads();

        {
            const int rsel = warp >> 2, h = warp & 3;
            const float s = sc[rsel][h * CELLS + lane];
            float v = s; int idx = lane;
            #pragma unroll
            for (int off = 16; off >= 1; off >>= 1) {
                float ov = __shfl_xor_sync(0xffffffffu, v, off);
                int   oi = __shfl_xor_sync(0xffffffffu, idx, off);
                if (ov > v || (ov == v && oi < idx)) { v = ov; idx = oi; }
            }
            const float v1 = v; const int i1 = idx;
            v = (lane == i1) ? -3.4e38f : s; idx = lane;
            #pragma unroll
            for (int off = 16; off >= 1; off >>= 1) {
                float ov = __shfl_xor_sync(0xffffffffu, v, off);
                int   oi = __shfl_xor_sync(0xffffffffu, idx, off);
                if (ov > v || (ov == v && oi < idx)) { v = ov; idx = oi; }
            }
            if (lane == 0) {
                g_sh[rsel][h] = 1.0f / (1.0f + expf(-(v1 - v)));
                w_sh[rsel][h] = i1;
                r_sh[rsel][h] = idx;
            }
        }
        __syncthreads();

        #pragma unroll
        for (int rsel = 0; rsel < 2; ++rsel) {
            float acc = lat[rsel][tid];
            #pragma unroll
            for (int h = 0; h < HEADS; ++h) {
                const float g = g_sh[rsel][h];
                acc += g          * cb[(h * CELLS + w_sh[rsel][h]) * DIM + tid]
                     + (1.0f - g) * cb[(h * CELLS + r_sh[rsel][h]) * DIM + tid];
            }
            g_reps[(row + rsel) * DIM + tid] = acc;
            g_bh16[(row + rsel) * DIM + tid] = __float2half_rn(acc);
        }
        __syncthreads();
    }
}

// =====================================================================
// Kernel 2: x -> fp16
// =====================================================================
__global__ void cvtx_kernel(const float* __restrict__ x) {
    const size_t i = ((size_t)blockIdx.x * 256 + threadIdx.x) * 8;
    float4 v0 = *(const float4*)(x + i);
    float4 v1 = *(const float4*)(x + i + 4);
    __half2 h01 = __floats2half2_rn(v0.x, v0.y);
    __half2 h23 = __floats2half2_rn(v0.z, v0.w);
    __half2 h45 = __floats2half2_rn(v1.x, v1.y);
    __half2 h67 = __floats2half2_rn(v1.z, v1.w);
    uint4 o;
    o.x = *(uint32_t*)&h01; o.y = *(uint32_t*)&h23;
    o.z = *(uint32_t*)&h45; o.w = *(uint32_t*)&h67;
    *(uint4*)&g_xh[i] = o;
}

// =====================================================================
// Kernel 3: reps -> fp16 transposed only
// =====================================================================
__global__ void trans_kernel() {
    __shared__ float tile[32][33];
    const int r0 = blockIdx.x * 32;     // NF dim
    const int c0 = blockIdx.y * 32;     // DIM dim
    const int tid = threadIdx.x;
    #pragma unroll
    for (int i = 0; i < 4; ++i) {
        const int idx = tid + i * 256;
        const int rr = idx >> 5, cc = idx & 31;
        tile[rr][cc] = g_reps[(r0 + rr) * DIM + c0 + cc];
    }
    __syncthreads();
    #pragma unroll
    for (int i = 0; i < 4; ++i) {
        const int idx = tid + i * 256;
        const int rr = idx >> 5, cc = idx & 31;
        g_bth[(size_t)(c0 + rr) * NF + r0 + cc] = __float2half_rn(tile[cc][rr]);
    }
}

// =====================================================================
// Tile copy: A, B — each 128 rows x 64 fp16 (8 chunks/row), swizzled.
// =====================================================================
__device__ __forceinline__ void copy_tiles(
    uint32_t base, int tid,
    const __half* A, size_t ap,
    const __half* B, size_t bp) {
    #pragma unroll
    for (int p = 0; p < 4; ++p) {
        const int idx = tid + p * 256;
        const int r = idx >> 3, c = idx & 7;
        const uint32_t off = tswz(r, c);
        const size_t g = (size_t)r;
        cp16(base + OFF_A + off, A + g * ap + c * 8);
        cp16(base + OFF_B + off, B + g * bp + c * 8);
    }
    cp_commit();
}

// =====================================================================
// mainloop macro: BM=128 BN=128 BK=64, 8 warps (2Mx4N), warp tile 64x32,
// single-pass fp16. 4 h-steps x 16 independent MMAs per iteration.
// 3-stage cp.async pipeline, one __syncthreads per iteration.
// =====================================================================
#define GEMM_MAINLOOP(sb, tid, A_, AP, B_, BP, NT, acc)                               \
{                                                                                     \
    const int lane = (tid) & 31, warp = (tid) >> 5;                                   \
    const int wm = warp & 1, wn = warp >> 1;                                          \
    const int rsub = lane & 15, csub = lane >> 4;                                     \
    int arow[4], brow[2];                                                             \
    _Pragma("unroll") for (int i = 0; i < 4; ++i) arow[i] = wm * 64 + i * 16 + rsub;  \
    _Pragma("unroll") for (int j = 0; j < 2; ++j) brow[j] = wn * 32 + j * 16 + rsub;  \
    copy_tiles((sb), (tid), (A_), (AP), (B_), (BP));                                  \
    copy_tiles((sb) + BUF_STRIDE, (tid), (A_) + 64, (AP), (B_) + 64, (BP));           \
    int bufi = 0;                                                                     \
    for (int t = 0; t < (NT); ++t) {                                                  \
        const uint32_t cb_ = (sb) + (uint32_t)bufi * BUF_STRIDE;                      \
        if (t + 1 < (NT)) cp_wait1(); else cp_wait0();                                \
        __syncthreads();                                                              \
        if (t + 2 < (NT)) {                                                           \
            const int kc = (t + 2) * 64;                                              \
            int wbuf = bufi + 2; if (wbuf >= N_STAGES) wbuf -= N_STAGES;              \
            copy_tiles((sb) + (uint32_t)wbuf * BUF_STRIDE, (tid),                     \
                       (A_) + kc, (AP), (B_) + kc, (BP));                             \
        }                                                                             \
        _Pragma("unroll") for (int h = 0; h < 4; ++h) {                               \
            uint32_t am[4][4], bm_[2][4];                                             \
            _Pragma("unroll") for (int i = 0; i < 4; ++i) {                           \
                const uint32_t ao = tswz(arow[i], 2 * h + csub);                      \
                ldsm4(am[i][0], am[i][1], am[i][2], am[i][3], cb_ + OFF_A + ao);      \
            }                                                                         \
            _Pragma("unroll") for (int j = 0; j < 2; ++j) {                           \
                const uint32_t bo = tswz(brow[j], 2 * h + csub);                      \
                ldsm4(bm_[j][0], bm_[j][1], bm_[j][2], bm_[j][3], cb_ + OFF_B + bo);  \
            }                                                                         \
            _Pragma("unroll") for (int i = 0; i < 4; ++i)                             \
            _Pragma("unroll") for (int j2 = 0; j2 < 2; ++j2)                          \
            _Pragma("unroll") for (int s = 0; s < 2; ++s)                             \
                mma16816(acc[i][j2 * 2 + s], am[i], bm_[j2][s], bm_[j2][s + 2]);      \
        }                                                                             \
        if (++bufi >= N_STAGES) bufi = 0;                                             \
    }                                                                                 \
}

// =====================================================================
// Kernel 4: gemm2: partial[bz] = X[:,kslice] @ reps[kslice,:]  (split-K=4)
// partials stored fp16 (halves epilogue + hconv DRAM traffic)
// =====================================================================
__global__ void __launch_bounds__(256, 2) gemm2_mm(void) {
    extern __shared__ char smem[];
    const uint32_t sb = smem_u32(smem);
    const int tid = threadIdx.x;
    const int bm = blockIdx.x, bn = blockIdx.y, bz = blockIdx.z;
    const int k0 = bz * (NF / SK2);
    const int NT = (NF / SK2) / 64;         // 32

    float acc[4][4][4];
    #pragma unroll
    for (int i = 0; i < 4; ++i)
        #pragma unroll
        for (int j = 0; j < 4; ++j)
            #pragma unroll
            for (int s = 0; s < 4; ++s) acc[i][j][s] = 0.0f;

    const __half* A = g_xh  + (size_t)(bm * 128) * NF + k0;
    const __half* B = g_bth + (size_t)(bn * 128) * NF + k0;

    GEMM_MAINLOOP(sb, tid, A, NF, B, NF, NT, acc);

    const int lane = tid & 31, warp = tid >> 5;
    const int wm = warp & 1, wn = warp >> 1;
    __half* P = g_part16[bz];
    const int l4 = lane >> 2, l2 = (lane & 3) * 2;
    #pragma unroll
    for (int i = 0; i < 4; ++i) {
        const int r0 = bm * 128 + wm * 64 + i * 16 + l4;
        #pragma unroll
        for (int j = 0; j < 4; ++j) {
            const int n = bn * 128 + wn * 32 + j * 8 + l2;
            *(__half2*)&P[(size_t)r0 * DIM + n] =
                __floats2half2_rn(acc[i][j][0], acc[i][j][1]);
            *(__half2*)&P[(size_t)(r0 + 8) * DIM + n] =
                __floats2half2_rn(acc[i][j][2], acc[i][j][3]);
        }
    }
}

// =====================================================================
// Kernel 5: sum split-K fp16 partials (fp32 accum) -> hidden fp16
// =====================================================================
__global__ void hconv_kernel() {
    const size_t i = ((size_t)blockIdx.x * 256 + threadIdx.x) * 8;
    float s[8];
    #pragma unroll
    for (int e = 0; e < 8; ++e) s[e] = 0.0f;
    #pragma unroll
    for (int z = 0; z < SK2; ++z) {
        uint4 raw = *(const uint4*)&g_part16[z][i];
        const __half2* hp = (const __half2*)&raw;
        #pragma unroll
        for (int q = 0; q < 4; ++q) {
            float2 f = __half22float2(hp[q]);
            s[2 * q]     += f.x;
            s[2 * q + 1] += f.y;
        }
    }
    uint4 o;
    __half2 o0 = __floats2half2_rn(s[0], s[1]);
    __half2 o1 = __floats2half2_rn(s[2], s[3]);
    __half2 o2 = __floats2half2_rn(s[4], s[5]);
    __half2 o3 = __floats2half2_rn(s[6], s[7]);
    o.x = *(uint32_t*)&o0; o.y = *(uint32_t*)&o1;
    o.z = *(uint32_t*)&o2; o.w = *(uint32_t*)&o3;
    *(uint4*)&g_ah[i] = o;
}

// =====================================================================
// Kernel 6: gemm3: out = relu(hidden @ reps^T + bias)   (R14 version)
// =====================================================================
__global__ void __launch_bounds__(256, 2) gemm3_mm(const float* __restrict__ bias,
                                                   float* __restrict__ out) {
    extern __shared__ char smem[];
    const uint32_t sb = smem_u32(smem);
    const int tid = threadIdx.x;
    const int bm = blockIdx.x, bn = blockIdx.y;
    const int NT = DIM / 64;                // 4

    float acc[4][4][4];
    #pragma unroll
    for (int i = 0; i < 4; ++i)
        #pragma unroll
        for (int j = 0; j < 4; ++j)
            #pragma unroll
            for (int s = 0; s < 4; ++s) acc[i][j][s] = 0.0f;

    const __half* A = g_ah   + (size_t)(bm * 128) * DIM;
    const __half* B = g_bh16 + (size_t)(bn * 128) * DIM;

    GEMM_MAINLOOP(sb, tid, A, DIM, B, DIM, NT, acc);

    const int lane = tid & 31, warp = tid >> 5;
    const int wm = warp & 1, wn = warp >> 1;
    const int l4 = lane >> 2, l2 = (lane & 3) * 2;
    #pragma unroll
    for (int i = 0; i < 4; ++i) {
        const int r0 = bm * 128 + wm * 64 + i * 16 + l4;
        #pragma unroll
        for (int j = 0; j < 4; ++j) {
            const int n = bn * 128 + wn * 32 + j * 8 + l2;
            const float b0 = bias[n], b1 = bias[n + 1];
            float2 v0 = make_float2(fmaxf(acc[i][j][0] + b0, 0.0f),
                                    fmaxf(acc[i][j][1] + b1, 0.0f));
            float2 v1 = make_float2(fmaxf(acc[i][j][2] + b0, 0.0f),
                                    fmaxf(acc[i][j][3] + b1, 0.0f));
            *(float2*)&out[(size_t)r0 * NF + n]       = v0;
            *(float2*)&out[(size_t)(r0 + 8) * NF + n] = v1;
        }
    }
}

// =====================================================================
extern "C" void kernel_launch(void* const* d_in, const int* in_sizes, int n_in,
                              void* d_out, int out_size) {
    const float* x    = (const float*)d_in[0];
    const float* proj = (const float*)d_in[1];
    const float* rw   = (const float*)d_in[2];
    const float* rb   = (const float*)d_in[3];
    const float* cb   = (const float*)d_in[4];
    const float* bias = (const float*)d_in[5];
    float* out = (float*)d_out;

    const int wbytes = HEADS * CELLS * DIM * (int)sizeof(float);   // 128 KB
    cudaFuncSetAttribute((const void*)reps_kernel,
                         cudaFuncAttributeMaxDynamicSharedMemorySize, wbytes);
    cudaFuncSetAttribute((const void*)gemm2_mm,
                         cudaFuncAttributeMaxDynamicSharedMemorySize, GEMM_SMEM);
    cudaFuncSetAttribute((const void*)gemm3_mm,
                         cudaFuncAttributeMaxDynamicSharedMemorySize, GEMM_SMEM);

    cvtx_kernel<<<(int)(((size_t)BATCH * NF / 8) / 256), 256>>>(x);
    reps_kernel<<<148, 256, wbytes>>>(proj, rw, rb, cb);
    trans_kernel<<<dim3(NF / 32, DIM / 32), 256>>>();

    gemm2_mm<<<dim3(BATCH / 128, DIM / 128, SK2), 256, GEMM_SMEM>>>();
    hconv_kernel<<<(BATCH * DIM / 8) / 256, 256>>>();
    gemm3_mm<<<dim3(BATCH / 128, NF / 128), 256, GEMM_SMEM>>>(bias, out);
}

// round 17
// speedup vs baseline: 1.0546x; 1.0546x over previous
#include <cuda_runtime.h>
#include <cuda_fp16.h>
#include <cstdint>

#define BATCH 4096
#define NF    8192
#define DIM   256
#define HEADS 4
#define CELLS 32
#define SK2   4            // gemm2 split-K

// ---------------- scratch (device globals; no allocs allowed) ----------------
__device__ __align__(16) __half g_xh[(size_t)BATCH * NF];   // x fp16 (67 MB)
__device__ float g_reps[NF * DIM];
__device__ __align__(16) __half g_bh16[NF * DIM];           // reps   [NF][DIM] fp16
__device__ __align__(16) __half g_bth[DIM * NF];            // reps^T [DIM][NF] fp16
__device__ __align__(16) __half g_part16[SK2][(size_t)BATCH * DIM];  // fp16 partials
__device__ __align__(16) __half g_ah[BATCH * DIM];          // hidden fp16

// ---------------- PTX helpers (base ISA only) ----------------
__device__ __forceinline__ uint32_t smem_u32(const void* p) {
    uint32_t a;
    asm("{ .reg .u64 t; cvta.to.shared.u64 t, %1; cvt.u32.u64 %0, t; }" : "=r"(a) : "l"(p));
    return a;
}
__device__ __forceinline__ void cp16(uint32_t d, const void* s) {
    asm volatile("cp.async.cg.shared.global [%0], [%1], 16;" :: "r"(d), "l"(s));
}
__device__ __forceinline__ void cp_commit() {
    asm volatile("cp.async.commit_group;" ::: "memory");
}
__device__ __forceinline__ void cp_wait0() {
    asm volatile("cp.async.wait_group 0;" ::: "memory");
}
__device__ __forceinline__ void cp_wait1() {
    asm volatile("cp.async.wait_group 1;" ::: "memory");
}
__device__ __forceinline__ void ldsm4(uint32_t& r0, uint32_t& r1, uint32_t& r2,
                                      uint32_t& r3, uint32_t a) {
    asm("ldmatrix.sync.aligned.m8n8.x4.shared.b16 {%0,%1,%2,%3}, [%4];"
        : "=r"(r0), "=r"(r1), "=r"(r2), "=r"(r3) : "r"(a));
}
__device__ __forceinline__ void mma16816(float* d, const uint32_t* a,
                                         uint32_t b0, uint32_t b1) {
    asm("mma.sync.aligned.m16n8k16.row.col.f32.f16.f16.f32 "
        "{%0,%1,%2,%3}, {%4,%5,%6,%7}, {%8,%9}, {%0,%1,%2,%3};"
        : "+f"(d[0]), "+f"(d[1]), "+f"(d[2]), "+f"(d[3])
        : "r"(a[0]), "r"(a[1]), "r"(a[2]), "r"(a[3]), "r"(b0), "r"(b1));
}

// smem tile: 128 rows x 64 fp16 = 128 B/row (8 16B chunks), swizzle c^(r&7)
#define OFF_A  0
#define OFF_B  16384
#define BUF_STRIDE 32768
#define N_STAGES 3
#define GEMM_SMEM (N_STAGES * BUF_STRIDE)    // 96 KB

__device__ __forceinline__ uint32_t tswz(int r, int c) {
    return (uint32_t)(r * 128 + ((c ^ (r & 7)) << 4));
}

// =====================================================================
// Kernel 1: reps — 2 rows per pass, smem partial-max reduction,
// fused straight fp16 output.
// =====================================================================
__global__ void reps_kernel(const float* __restrict__ proj,
                            const float* __restrict__ rw,
                            const float* __restrict__ rb,
                            const float* __restrict__ cb) {
    extern __shared__ float Wsh[];              // HEADS*CELLS*DIM floats (128KB)
    __shared__ float lat[2][DIM];
    __shared__ float part[2][HEADS * CELLS][33];
    __shared__ float sc[2][HEADS * CELLS];
    __shared__ float g_sh[2][HEADS];
    __shared__ int   w_sh[2][HEADS];
    __shared__ int   r_sh[2][HEADS];

    const int tid  = threadIdx.x;
    const int lane = tid & 31;
    const int warp = tid >> 5;

    for (int i = tid; i < HEADS * CELLS * DIM; i += 256)
        Wsh[i] = rw[i];
    __syncthreads();

    for (int row = blockIdx.x * 2; row < NF; row += gridDim.x * 2) {
        lat[0][tid] = proj[row * DIM + tid];
        lat[1][tid] = proj[(row + 1) * DIM + tid];
        __syncthreads();

        float la0[8], la1[8];
        #pragma unroll
        for (int i = 0; i < 8; ++i) {
            la0[i] = lat[0][lane + 32 * i];
            la1[i] = lat[1][lane + 32 * i];
        }

        #pragma unroll 1
        for (int pi = 0; pi < 16; ++pi) {
            const int p = warp * 16 + pi;
            const float* wrow = &Wsh[p * DIM];
            float m0 = -3.4e38f, m1 = -3.4e38f;
            #pragma unroll
            for (int i = 0; i < 8; ++i) {
                const float w = wrow[lane + 32 * i];
                m0 = fmaxf(m0, la0[i] + w);
                m1 = fmaxf(m1, la1[i] + w);
            }
            part[0][p][lane] = m0;
            part[1][p][lane] = m1;
        }
        __syncthreads();

        {
            const int rsel = tid >> 7;          // 0 or 1
            const int p = tid & 127;
            float m = -3.4e38f;
            #pragma unroll
            for (int i = 0; i < 32; ++i) m = fmaxf(m, part[rsel][p][i]);
            sc[rsel][p] = m + rb[p];
        }
        __syncthreads();

        {
            const int rsel = warp >> 2, h = warp & 3;
            const float s = sc[rsel][h * CELLS + lane];
            float v = s; int idx = lane;
            #pragma unroll
            for (int off = 16; off >= 1; off >>= 1) {
                float ov = __shfl_xor_sync(0xffffffffu, v, off);
                int   oi = __shfl_xor_sync(0xffffffffu, idx, off);
                if (ov > v || (ov == v && oi < idx)) { v = ov; idx = oi; }
            }
            const float v1 = v; const int i1 = idx;
            v = (lane == i1) ? -3.4e38f : s; idx = lane;
            #pragma unroll
            for (int off = 16; off >= 1; off >>= 1) {
                float ov = __shfl_xor_sync(0xffffffffu, v, off);
                int   oi = __shfl_xor_sync(0xffffffffu, idx, off);
                if (ov > v || (ov == v && oi < idx)) { v = ov; idx = oi; }
            }
            if (lane == 0) {
                g_sh[rsel][h] = 1.0f / (1.0f + expf(-(v1 - v)));
                w_sh[rsel][h] = i1;
                r_sh[rsel][h] = idx;
            }
        }
        __syncthreads();

        #pragma unroll
        for (int rsel = 0; rsel < 2; ++rsel) {
            float acc = lat[rsel][tid];
            #pragma unroll
            for (int h = 0; h < HEADS; ++h) {
                const float g = g_sh[rsel][h];
                acc += g          * cb[(h * CELLS + w_sh[rsel][h]) * DIM + tid]
                     + (1.0f - g) * cb[(h * CELLS + r_sh[rsel][h]) * DIM + tid];
            }
            g_reps[(row + rsel) * DIM + tid] = acc;
            g_bh16[(row + rsel) * DIM + tid] = __float2half_rn(acc);
        }
        __syncthreads();
    }
}

// =====================================================================
// Kernel 2: x -> fp16
// =====================================================================
__global__ void cvtx_kernel(const float* __restrict__ x) {
    const size_t i = ((size_t)blockIdx.x * 256 + threadIdx.x) * 8;
    float4 v0 = *(const float4*)(x + i);
    float4 v1 = *(const float4*)(x + i + 4);
    __half2 h01 = __floats2half2_rn(v0.x, v0.y);
    __half2 h23 = __floats2half2_rn(v0.z, v0.w);
    __half2 h45 = __floats2half2_rn(v1.x, v1.y);
    __half2 h67 = __floats2half2_rn(v1.z, v1.w);
    uint4 o;
    o.x = *(uint32_t*)&h01; o.y = *(uint32_t*)&h23;
    o.z = *(uint32_t*)&h45; o.w = *(uint32_t*)&h67;
    *(uint4*)&g_xh[i] = o;
}

// =====================================================================
// Kernel 3: reps -> fp16 transposed only
// =====================================================================
__global__ void trans_kernel() {
    __shared__ float tile[32][33];
    const int r0 = blockIdx.x * 32;     // NF dim
    const int c0 = blockIdx.y * 32;     // DIM dim
    const int tid = threadIdx.x;
    #pragma unroll
    for (int i = 0; i < 4; ++i) {
        const int idx = tid + i * 256;
        const int rr = idx >> 5, cc = idx & 31;
        tile[rr][cc] = g_reps[(r0 + rr) * DIM + c0 + cc];
    }
    __syncthreads();
    #pragma unroll
    for (int i = 0; i < 4; ++i) {
        const int idx = tid + i * 256;
        const int rr = idx >> 5, cc = idx & 31;
        g_bth[(size_t)(c0 + rr) * NF + r0 + cc] = __float2half_rn(tile[cc][rr]);
    }
}

// =====================================================================
// Tile copy: A, B — each 128 rows x 64 fp16 (8 chunks/row), swizzled.
// =====================================================================
__device__ __forceinline__ void copy_tiles(
    uint32_t base, int tid,
    const __half* A, size_t ap,
    const __half* B, size_t bp) {
    #pragma unroll
    for (int p = 0; p < 4; ++p) {
        const int idx = tid + p * 256;
        const int r = idx >> 3, c = idx & 7;
        const uint32_t off = tswz(r, c);
        const size_t g = (size_t)r;
        cp16(base + OFF_A + off, A + g * ap + c * 8);
        cp16(base + OFF_B + off, B + g * bp + c * 8);
    }
    cp_commit();
}

// =====================================================================
// mainloop macro: BM=128 BN=128 BK=64, 8 warps (2Mx4N), warp tile 64x32,
// single-pass fp16. 4 h-steps x 16 independent MMAs per iteration.
// 3-stage cp.async pipeline, one __syncthreads per iteration.
// =====================================================================
#define GEMM_MAINLOOP(sb, tid, A_, AP, B_, BP, NT, acc)                               \
{                                                                                     \
    const int lane = (tid) & 31, warp = (tid) >> 5;                                   \
    const int wm = warp & 1, wn = warp >> 1;                                          \
    const int rsub = lane & 15, csub = lane >> 4;                                     \
    int arow[4], brow[2];                                                             \
    _Pragma("unroll") for (int i = 0; i < 4; ++i) arow[i] = wm * 64 + i * 16 + rsub;  \
    _Pragma("unroll") for (int j = 0; j < 2; ++j) brow[j] = wn * 32 + j * 16 + rsub;  \
    copy_tiles((sb), (tid), (A_), (AP), (B_), (BP));                                  \
    copy_tiles((sb) + BUF_STRIDE, (tid), (A_) + 64, (AP), (B_) + 64, (BP));           \
    int bufi = 0;                                                                     \
    for (int t = 0; t < (NT); ++t) {                                                  \
        const uint32_t cb_ = (sb) + (uint32_t)bufi * BUF_STRIDE;                      \
        if (t + 1 < (NT)) cp_wait1(); else cp_wait0();                                \
        __syncthreads();                                                              \
        if (t + 2 < (NT)) {                                                           \
            const int kc = (t + 2) * 64;                                              \
            int wbuf = bufi + 2; if (wbuf >= N_STAGES) wbuf -= N_STAGES;              \
            copy_tiles((sb) + (uint32_t)wbuf * BUF_STRIDE, (tid),                     \
                       (A_) + kc, (AP), (B_) + kc, (BP));                             \
        }                                                                             \
        _Pragma("unroll") for (int h = 0; h < 4; ++h) {                               \
            uint32_t am[4][4], bm_[2][4];                                             \
            _Pragma("unroll") for (int i = 0; i < 4; ++i) {                           \
                const uint32_t ao = tswz(arow[i], 2 * h + csub);                      \
                ldsm4(am[i][0], am[i][1], am[i][2], am[i][3], cb_ + OFF_A + ao);      \
            }                                                                         \
            _Pragma("unroll") for (int j = 0; j < 2; ++j) {                           \
                const uint32_t bo = tswz(brow[j], 2 * h + csub);                      \
                ldsm4(bm_[j][0], bm_[j][1], bm_[j][2], bm_[j][3], cb_ + OFF_B + bo);  \
            }                                                                         \
            _Pragma("unroll") for (int i = 0; i < 4; ++i)                             \
            _Pragma("unroll") for (int j2 = 0; j2 < 2; ++j2)                          \
            _Pragma("unroll") for (int s = 0; s < 2; ++s)                             \
                mma16816(acc[i][j2 * 2 + s], am[i], bm_[j2][s], bm_[j2][s + 2]);      \
        }                                                                             \
        if (++bufi >= N_STAGES) bufi = 0;                                             \
    }                                                                                 \
}

// =====================================================================
// Kernel 4: gemm2: partial[bz] = X[:,kslice] @ reps[kslice,:]  (split-K=4)
// partials stored fp16
// =====================================================================
__global__ void __launch_bounds__(256, 2) gemm2_mm(void) {
    extern __shared__ char smem[];
    const uint32_t sb = smem_u32(smem);
    const int tid = threadIdx.x;
    const int bm = blockIdx.x, bn = blockIdx.y, bz = blockIdx.z;
    const int k0 = bz * (NF / SK2);
    const int NT = (NF / SK2) / 64;         // 32

    float acc[4][4][4];
    #pragma unroll
    for (int i = 0; i < 4; ++i)
        #pragma unroll
        for (int j = 0; j < 4; ++j)
            #pragma unroll
            for (int s = 0; s < 4; ++s) acc[i][j][s] = 0.0f;

    const __half* A = g_xh  + (size_t)(bm * 128) * NF + k0;
    const __half* B = g_bth + (size_t)(bn * 128) * NF + k0;

    GEMM_MAINLOOP(sb, tid, A, NF, B, NF, NT, acc);

    const int lane = tid & 31, warp = tid >> 5;
    const int wm = warp & 1, wn = warp >> 1;
    __half* P = g_part16[bz];
    const int l4 = lane >> 2, l2 = (lane & 3) * 2;
    #pragma unroll
    for (int i = 0; i < 4; ++i) {
        const int r0 = bm * 128 + wm * 64 + i * 16 + l4;
        #pragma unroll
        for (int j = 0; j < 4; ++j) {
            const int n = bn * 128 + wn * 32 + j * 8 + l2;
            *(__half2*)&P[(size_t)r0 * DIM + n] =
                __floats2half2_rn(acc[i][j][0], acc[i][j][1]);
            *(__half2*)&P[(size_t)(r0 + 8) * DIM + n] =
                __floats2half2_rn(acc[i][j][2], acc[i][j][3]);
        }
    }
}

// =====================================================================
// Kernel 5: sum split-K fp16 partials (fp32 accum) -> hidden fp16
// =====================================================================
__global__ void hconv_kernel() {
    const size_t i = ((size_t)blockIdx.x * 256 + threadIdx.x) * 8;
    float s[8];
    #pragma unroll
    for (int e = 0; e < 8; ++e) s[e] = 0.0f;
    #pragma unroll
    for (int z = 0; z < SK2; ++z) {
        uint4 raw = *(const uint4*)&g_part16[z][i];
        const __half2* hp = (const __half2*)&raw;
        #pragma unroll
        for (int q = 0; q < 4; ++q) {
            float2 f = __half22float2(hp[q]);
            s[2 * q]     += f.x;
            s[2 * q + 1] += f.y;
        }
    }
    uint4 o;
    __half2 o0 = __floats2half2_rn(s[0], s[1]);
    __half2 o1 = __floats2half2_rn(s[2], s[3]);
    __half2 o2 = __floats2half2_rn(s[4], s[5]);
    __half2 o3 = __floats2half2_rn(s[6], s[7]);
    o.x = *(uint32_t*)&o0; o.y = *(uint32_t*)&o1;
    o.z = *(uint32_t*)&o2; o.w = *(uint32_t*)&o3;
    *(uint4*)&g_ah[i] = o;
}

// =====================================================================
// Kernel 6: gemm3: out = relu(hidden @ reps^T + bias)
// =====================================================================
__global__ void __launch_bounds__(256, 2) gemm3_mm(const float* __restrict__ bias,
                                                   float* __restrict__ out) {
    extern __shared__ char smem[];
    const uint32_t sb = smem_u32(smem);
    const int tid = threadIdx.x;
    const int bm = blockIdx.x, bn = blockIdx.y;
    const int NT = DIM / 64;                // 4

    float acc[4][4][4];
    #pragma unroll
    for (int i = 0; i < 4; ++i)
        #pragma unroll
        for (int j = 0; j < 4; ++j)
            #pragma unroll
            for (int s = 0; s < 4; ++s) acc[i][j][s] = 0.0f;

    const __half* A = g_ah   + (size_t)(bm * 128) * DIM;
    const __half* B = g_bh16 + (size_t)(bn * 128) * DIM;

    GEMM_MAINLOOP(sb, tid, A, DIM, B, DIM, NT, acc);

    const int lane = tid & 31, warp = tid >> 5;
    const int wm = warp & 1, wn = warp >> 1;
    const int l4 = lane >> 2, l2 = (lane & 3) * 2;
    #pragma unroll
    for (int i = 0; i < 4; ++i) {
        const int r0 = bm * 128 + wm * 64 + i * 16 + l4;
        #pragma unroll
        for (int j = 0; j < 4; ++j) {
            const int n = bn * 128 + wn * 32 + j * 8 + l2;
            const float b0 = bias[n], b1 = bias[n + 1];
            float2 v0 = make_float2(fmaxf(acc[i][j][0] + b0, 0.0f),
                                    fmaxf(acc[i][j][1] + b1, 0.0f));
            float2 v1 = make_float2(fmaxf(acc[i][j][2] + b0, 0.0f),
                                    fmaxf(acc[i][j][3] + b1, 0.0f));
            *(float2*)&out[(size_t)r0 * NF + n]       = v0;
            *(float2*)&out[(size_t)(r0 + 8) * NF + n] = v1;
        }
    }
}

// =====================================================================
extern "C" void kernel_launch(void* const* d_in, const int* in_sizes, int n_in,
                              void* d_out, int out_size) {
    const float* x    = (const float*)d_in[0];
    const float* proj = (const float*)d_in[1];
    const float* rw   = (const float*)d_in[2];
    const float* rb   = (const float*)d_in[3];
    const float* cb   = (const float*)d_in[4];
    const float* bias = (const float*)d_in[5];
    float* out = (float*)d_out;

    const int wbytes = HEADS * CELLS * DIM * (int)sizeof(float);   // 128 KB
    cudaFuncSetAttribute((const void*)reps_kernel,
                         cudaFuncAttributeMaxDynamicSharedMemorySize, wbytes);
    cudaFuncSetAttribute((const void*)gemm2_mm,
                         cudaFuncAttributeMaxDynamicSharedMemorySize, GEMM_SMEM);
    cudaFuncSetAttribute((const void*)gemm3_mm,
                         cudaFuncAttributeMaxDynamicSharedMemorySize, GEMM_SMEM);

    // ---- fork: cvtx (DRAM-bound, depends only on x) runs concurrently
    //      with reps+trans (compute-bound) via event fork/join capture ----
    cudaStream_t s2;
    cudaStreamCreateWithFlags(&s2, cudaStreamNonBlocking);
    cudaEvent_t e_fork, e_join;
    cudaEventCreateWithFlags(&e_fork, cudaEventDisableTiming);
    cudaEventCreateWithFlags(&e_join, cudaEventDisableTiming);

    cudaEventRecord(e_fork, 0);
    cudaStreamWaitEvent(s2, e_fork, 0);
    cvtx_kernel<<<(int)(((size_t)BATCH * NF / 8) / 256), 256, 0, s2>>>(x);
    cudaEventRecord(e_join, s2);

    reps_kernel<<<148, 256, wbytes>>>(proj, rw, rb, cb);
    trans_kernel<<<dim3(NF / 32, DIM / 32), 256>>>();

    cudaStreamWaitEvent(0, e_join, 0);

    gemm2_mm<<<dim3(BATCH / 128, DIM / 128, SK2), 256, GEMM_SMEM>>>();
    hconv_kernel<<<(BATCH * DIM / 8) / 256, 256>>>();
    gemm3_mm<<<dim3(BATCH / 128, NF / 128), 256, GEMM_SMEM>>>(bias, out);

    cudaEventDestroy(e_fork);
    cudaEventDestroy(e_join);
    cudaStreamDestroy(s2);
}